// round 15
// baseline (speedup 1.0000x reference)
#include <cuda_runtime.h>
#include <cuda_fp16.h>
#include <cstdint>

// ---------------------------------------------------------------------------
// Florence2 window attention — all matmuls on mma.sync (fp16 in, fp32 acc).
// R15: attention inner loop interleaves QK-mma/exp with PV-mma per k-tile
// (kills the 36-reg score array; keeps the tensor pipe fed end-to-end).
// GEMMs: R12-proven 512-thread config (established legacy-HMMA floor).
// ---------------------------------------------------------------------------

#define NWIN   128
#define NTOK   144
#define DIM    512
#define NHEAD  16
#define HDIM   32
#define MTOT   (NWIN * NTOK)     // 18432
#define NQKV   1536

#define SROW   72                // hgemm smem row stride in halves (144B)
#define BUFH  (128 * SROW)       // halves per buffer (per operand)
#define TSTR  (16 * SROW * 2)    // smem bytes between 16-row tiles

// ---------------- scratch (device globals; device-code refs only) ----------
__device__ __align__(16) __half g_x  [MTOT * DIM];
__device__ __align__(16) __half g_wq [NQKV * DIM];
__device__ __align__(16) __half g_wp [DIM * DIM];
__device__ __align__(16) __half g_qh [NWIN * NHEAD * NTOK * HDIM];
__device__ __align__(16) __half g_kh [NWIN * NHEAD * NTOK * HDIM];
__device__ __align__(16) __half g_vT [NWIN * NHEAD * HDIM * NTOK];
__device__ __align__(16) __half g_ao [MTOT * DIM];

// ---------------- PTX helpers ----------------------------------------------
__device__ __forceinline__ uint32_t smem_u32(const void* p) {
    uint32_t a;
    asm("{ .reg .u64 t; cvta.to.shared.u64 t, %1; cvt.u32.u64 %0, t; }" : "=r"(a) : "l"(p));
    return a;
}
__device__ __forceinline__ void cp_async16(uint32_t s, const void* g) {
    asm volatile("cp.async.cg.shared.global [%0], [%1], 16;" :: "r"(s), "l"(g));
}
__device__ __forceinline__ void cp_commit() { asm volatile("cp.async.commit_group;"); }
__device__ __forceinline__ void cp_wait0()  { asm volatile("cp.async.wait_group 0;"); }

__device__ __forceinline__ void ldsm_x4(uint32_t* r, uint32_t addr) {
    asm volatile("ldmatrix.sync.aligned.m8n8.x4.shared.b16 {%0,%1,%2,%3}, [%4];"
        : "=r"(r[0]), "=r"(r[1]), "=r"(r[2]), "=r"(r[3]) : "r"(addr));
}
__device__ __forceinline__ void mma16816(float* d, const uint32_t* a,
                                         uint32_t b0, uint32_t b1) {
    asm volatile("mma.sync.aligned.m16n8k16.row.col.f32.f16.f16.f32 "
        "{%0,%1,%2,%3}, {%4,%5,%6,%7}, {%8,%9}, {%0,%1,%2,%3};"
        : "+f"(d[0]), "+f"(d[1]), "+f"(d[2]), "+f"(d[3])
        : "r"(a[0]), "r"(a[1]), "r"(a[2]), "r"(a[3]), "r"(b0), "r"(b1));
}

__device__ __forceinline__ int hidden_row_off(int m) {
    int win = m / NTOK, t = m % NTOK;
    int b = win >> 4, yw = (win >> 2) & 3, xw = win & 3;
    int y = yw * 12 + t / 12;
    int x = xw * 12 + t % 12;
    return ((b * 48 + y) * 48 + x) * DIM;
}

// ---------------------------------------------------------------------------
// merged conversion kernel: blocks [0, NXB) convert X; rest transpose weights
// ---------------------------------------------------------------------------
#define NXB (MTOT * 64 / 256)            // 4608
#define NWB ((NQKV / 32 + DIM / 32) * (DIM / 32))   // 1024

__global__ void convert_all_kernel(const float* __restrict__ hidden,
                                   const float* __restrict__ Wq,
                                   const float* __restrict__ Wp) {
    const int tid = threadIdx.x;
    if (blockIdx.x < NXB) {
        int idx = blockIdx.x * 256 + tid;
        int m = idx >> 6, seg = idx & 63;
        const float* src = hidden + hidden_row_off(m) + seg * 8;
        float4 f0 = *(const float4*)src;
        float4 f1 = *(const float4*)(src + 4);
        __align__(16) __half h[8];
        h[0] = __float2half(f0.x); h[1] = __float2half(f0.y);
        h[2] = __float2half(f0.z); h[3] = __float2half(f0.w);
        h[4] = __float2half(f1.x); h[5] = __float2half(f1.y);
        h[6] = __float2half(f1.z); h[7] = __float2half(f1.w);
        *(uint4*)&g_x[m * DIM + seg * 8] = *(uint4*)h;
        return;
    }
    __shared__ float t[32][33];
    const int r = blockIdx.x - NXB;
    const int bx = r & 63, by = r >> 6;
    const bool isP = bx >= (NQKV / 32);
    const float* __restrict__ W = isP ? Wp : Wq;
    const int N = isP ? DIM : NQKV;
    __half* __restrict__ outT = isP ? g_wp : g_wq;
    const int n0 = (isP ? bx - NQKV / 32 : bx) * 32;
    const int k0 = by * 32;
    const int tx = tid & 31, ty = tid >> 5;   // 32 x 8
    #pragma unroll
    for (int j = 0; j < 4; ++j)
        t[ty + 8 * j][tx] = W[(k0 + ty + 8 * j) * N + n0 + tx];
    __syncthreads();
    #pragma unroll
    for (int j = 0; j < 4; ++j)
        outT[(n0 + ty + 8 * j) * DIM + k0 + tx] = __float2half(t[tx][ty + 8 * j]);
}

// ---------------------------------------------------------------------------
// 512-thread HGEMM mainloop (16 warps, warp tile 32x32), f32-acc (R12-proven).
// ---------------------------------------------------------------------------
__device__ __forceinline__ void hgemm512_tile(
    const __half* __restrict__ A, const __half* __restrict__ B,
    int m0, int n0, float acc[2][4][4],
    __half (*sA)[BUFH], __half (*sB)[BUFH])
{
    const int tid = threadIdx.x;
    const int lane = tid & 31, wid = tid >> 5;
    const int wm = (wid & 3) * 32, wn = (wid >> 2) * 32;

    const uint32_t aBase = smem_u32(&sA[0][0]);
    const uint32_t bBase = smem_u32(&sB[0][0]);

    const __half* gA0 = A + (m0 + (tid >> 3)) * DIM + (tid & 7) * 8;
    const __half* gB0 = B + (n0 + (tid >> 3)) * DIM + (tid & 7) * 8;
    const uint32_t stA0 = aBase + (tid >> 3) * (SROW * 2) + (tid & 7) * 16;
    const uint32_t stB0 = bBase + (tid >> 3) * (SROW * 2) + (tid & 7) * 16;
    const int GS2 = 64 * DIM;
    const int SS2 = 64 * SROW * 2;

    const int la = lane & 7;
    const uint32_t aFrag0 = aBase + (wm + la + ((lane & 8) ? 8 : 0)) * (SROW * 2)
                          + (((lane & 16) ? 8 : 0)) * 2;
    const uint32_t bFrag0 = bBase + (wn + la + ((lane & 16) ? 8 : 0)) * (SROW * 2)
                          + (((lane & 8) ? 8 : 0)) * 2;

    cp_async16(stA0, gA0);             cp_async16(stB0, gB0);
    cp_async16(stA0 + SS2, gA0 + GS2); cp_async16(stB0 + SS2, gB0 + GS2);
    cp_commit();

    #pragma unroll 1
    for (int ch = 0; ch < 8; ++ch) {
        cp_wait0();
        __syncthreads();

        if (ch < 7) {
            const uint32_t bo = ((ch + 1) & 1) * (BUFH * 2);
            const int ko = (ch + 1) * 64;
            cp_async16(stA0 + bo, gA0 + ko);
            cp_async16(stB0 + bo, gB0 + ko);
            cp_async16(stA0 + bo + SS2, gA0 + ko + GS2);
            cp_async16(stB0 + bo + SS2, gB0 + ko + GS2);
            cp_commit();
        }

        const uint32_t aF = aFrag0 + (ch & 1) * (BUFH * 2);
        const uint32_t bF = bFrag0 + (ch & 1) * (BUFH * 2);
        #pragma unroll
        for (int s = 0; s < 4; ++s) {
            const uint32_t kb = s * 32;
            uint32_t a[2][4], b[2][4];
            ldsm_x4(a[0], aF + kb);
            ldsm_x4(a[1], aF + kb + TSTR);
            ldsm_x4(b[0], bF + kb);
            ldsm_x4(b[1], bF + kb + TSTR);
            #pragma unroll
            for (int i = 0; i < 2; ++i) {
                mma16816(acc[i][0], a[i], b[0][0], b[0][1]);
                mma16816(acc[i][1], a[i], b[0][2], b[0][3]);
                mma16816(acc[i][2], a[i], b[1][0], b[1][1]);
                mma16816(acc[i][3], a[i], b[1][2], b[1][3]);
            }
        }
    }
}

// ---------------------------------------------------------------------------
// Kernel: QKV GEMM — 512 threads (R12-proven).
// ---------------------------------------------------------------------------
__global__ __launch_bounds__(512, 2)
void qkv_hgemm_kernel(const float* __restrict__ bias)
{
    __shared__ __align__(16) __half sA[2][BUFH];
    __shared__ __align__(16) __half sB[2][BUFH];

    float acc[2][4][4] = {};
    const int m0 = blockIdx.y * 128, n0 = blockIdx.x * 128;
    hgemm512_tile(g_x, g_wq, m0, n0, acc, sA, sB);

    const int tid = threadIdx.x, lane = tid & 31, wid = tid >> 5;
    const int g = lane >> 2, t = lane & 3;
    const int wm = (wid & 3) * 32, wn = (wid >> 2) * 32;
    const float scale = 0.1767766952966369f;   // 32^-0.5

    #pragma unroll
    for (int i = 0; i < 2; ++i) {
        #pragma unroll
        for (int h = 0; h < 2; ++h) {
            const int m = m0 + wm + i * 16 + h * 8 + g;
            const int win = m / NTOK, tok = m % NTOK;
            #pragma unroll
            for (int j = 0; j < 4; ++j) {
                const int n = n0 + wn + j * 8 + 2 * t;
                const int sel = n >> 9, head = (n >> 5) & 15, d = n & 31;
                const int wh = (win << 4) + head;
                float vx = acc[i][j][h * 2 + 0] + bias[n + 0];
                float vy = acc[i][j][h * 2 + 1] + bias[n + 1];
                if (sel == 0) {
                    *(__half2*)&g_qh[(wh * NTOK + tok) * HDIM + d] =
                        __floats2half2_rn(vx * scale, vy * scale);
                } else if (sel == 1) {
                    *(__half2*)&g_kh[(wh * NTOK + tok) * HDIM + d] =
                        __floats2half2_rn(vx, vy);
                } else {
                    g_vT[(wh * HDIM + d    ) * NTOK + tok] = __float2half(vx);
                    g_vT[(wh * HDIM + d + 1) * NTOK + tok] = __float2half(vy);
                }
            }
        }
    }
}

// ---------------------------------------------------------------------------
// Kernel: tensor-core attention — R15: QK/exp and PV interleaved per k-tile.
// 288 threads, 9 warps, 1 Q-tile/warp. Q frags direct from gmem.
// ---------------------------------------------------------------------------
#define QROW 40     // sK row stride (halves)
#define VROW 152    // sVT row stride (halves)

__global__ __launch_bounds__(288)
void attn_mma_kernel()
{
    __shared__ __align__(16) __half sK[NTOK * QROW];
    __shared__ __align__(16) __half sVT[HDIM * VROW];

    const int wh = blockIdx.x;
    const int tid = threadIdx.x, lane = tid & 31, wid = tid >> 5;
    const int g = lane >> 2, t = lane & 3;

    const __half* qp = g_qh + wh * (NTOK * HDIM);
    const __half* kp = g_kh + wh * (NTOK * HDIM);
    const __half* vp = g_vT + wh * (HDIM * NTOK);

    for (int seg = tid; seg < 576; seg += 288) {
        int row = seg >> 2, sub = seg & 3;
        *(uint4*)&sK[row * QROW + sub * 8] = *(const uint4*)(kp + row * HDIM + sub * 8);
        int vrow = seg / 18, vsub = seg - vrow * 18;
        *(uint4*)&sVT[vrow * VROW + vsub * 8] = *(const uint4*)(vp + vrow * NTOK + vsub * 8);
    }
    __syncthreads();

    const int win = wh >> 4, head = wh & 15;
    const int r = wid * 16 + g;            // warp -> its 16-row Q tile

    // Q A-fragments straight from gmem (32-bit aligned, L2-hot)
    uint32_t qa[2][4];
    #pragma unroll
    for (int s = 0; s < 2; ++s) {
        const int c = s * 16 + 2 * t;
        qa[s][0] = *(const uint32_t*)&qp[ r      * HDIM + c    ];
        qa[s][1] = *(const uint32_t*)&qp[(r + 8) * HDIM + c    ];
        qa[s][2] = *(const uint32_t*)&qp[ r      * HDIM + c + 8];
        qa[s][3] = *(const uint32_t*)&qp[(r + 8) * HDIM + c + 8];
    }

    float acc[4][4] = {};
    float sum0 = 0.f, sum1 = 0.f;

    #pragma unroll
    for (int kk = 0; kk < 9; ++kk) {
        uint32_t pa[4];                    // P A-fragment for this 16-token k-tile
        #pragma unroll
        for (int jj = 0; jj < 2; ++jj) {
            const int j = 2 * kk + jj;
            float sc[4] = {};
            const int rn = 8 * j + g;
            #pragma unroll
            for (int s = 0; s < 2; ++s) {
                const int c = s * 16 + 2 * t;
                uint32_t b0 = *(const uint32_t*)&sK[rn * QROW + c    ];
                uint32_t b1 = *(const uint32_t*)&sK[rn * QROW + c + 8];
                mma16816(sc, qa[s], b0, b1);
            }
            float e0 = __expf(sc[0]), e1 = __expf(sc[1]);
            float e2 = __expf(sc[2]), e3 = __expf(sc[3]);
            sum0 += e0 + e1; sum1 += e2 + e3;
            __half2 p01 = __floats2half2_rn(e0, e1);
            __half2 p23 = __floats2half2_rn(e2, e3);
            pa[2 * jj + 0] = *(uint32_t*)&p01;
            pa[2 * jj + 1] = *(uint32_t*)&p23;
        }
        #pragma unroll
        for (int nd = 0; nd < 4; ++nd) {
            const int rn = 8 * nd + g;
            uint32_t b0 = *(const uint32_t*)&sVT[rn * VROW + kk * 16 + 2 * t    ];
            uint32_t b1 = *(const uint32_t*)&sVT[rn * VROW + kk * 16 + 2 * t + 8];
            mma16816(acc[nd], pa, b0, b1);
        }
    }

    sum0 += __shfl_xor_sync(0xffffffffu, sum0, 1);
    sum0 += __shfl_xor_sync(0xffffffffu, sum0, 2);
    sum1 += __shfl_xor_sync(0xffffffffu, sum1, 1);
    sum1 += __shfl_xor_sync(0xffffffffu, sum1, 2);

    const float inv0 = 1.f / sum0, inv1 = 1.f / sum1;
    __half* o0 = g_ao + (win * NTOK + r) * DIM + head * HDIM;
    __half* o1 = o0 + 8 * DIM;
    #pragma unroll
    for (int nd = 0; nd < 4; ++nd) {
        const int d = 8 * nd + 2 * t;
        *(__half2*)&o0[d] = __floats2half2_rn(acc[nd][0] * inv0, acc[nd][1] * inv0);
        *(__half2*)&o1[d] = __floats2half2_rn(acc[nd][2] * inv1, acc[nd][3] * inv1);
    }
}

// ---------------------------------------------------------------------------
// Kernel: proj GEMM — 512 threads (R12-proven).
// ---------------------------------------------------------------------------
__global__ __launch_bounds__(512, 2)
void proj_hgemm_kernel(const float* __restrict__ bias, float* __restrict__ out)
{
    __shared__ __align__(16) __half sA[2][BUFH];
    __shared__ __align__(16) __half sB[2][BUFH];

    float acc[2][4][4] = {};
    const int m0 = blockIdx.y * 128, n0 = blockIdx.x * 128;
    hgemm512_tile(g_ao, g_wp, m0, n0, acc, sA, sB);

    const int tid = threadIdx.x, lane = tid & 31, wid = tid >> 5;
    const int g = lane >> 2, t = lane & 3;
    const int wm = (wid & 3) * 32, wn = (wid >> 2) * 32;

    #pragma unroll
    for (int i = 0; i < 2; ++i) {
        #pragma unroll
        for (int h = 0; h < 2; ++h) {
            const int m = m0 + wm + i * 16 + h * 8 + g;
            const int win = m / NTOK, tok = m % NTOK;
            const int b = win >> 4, yw = (win >> 2) & 3, xw = win & 3;
            const int y = yw * 12 + tok / 12;
            const int x = xw * 12 + tok % 12;
            float* orow = out + ((b * 2304 + y * 48 + x) << 9);
            #pragma unroll
            for (int j = 0; j < 4; ++j) {
                const int n = n0 + wn + j * 8 + 2 * t;
                float2 v;
                v.x = acc[i][j][h * 2 + 0] + bias[n + 0];
                v.y = acc[i][j][h * 2 + 1] + bias[n + 1];
                *(float2*)&orow[n] = v;
            }
        }
    }
}

// ---------------------------------------------------------------------------
extern "C" void kernel_launch(void* const* d_in, const int* in_sizes, int n_in,
                              void* d_out, int out_size)
{
    const float* hidden = (const float*)d_in[0];
    const float* qkv_w  = (const float*)d_in[1];
    const float* qkv_b  = (const float*)d_in[2];
    const float* proj_w = (const float*)d_in[3];
    const float* proj_b = (const float*)d_in[4];
    float* out = (float*)d_out;

    convert_all_kernel<<<NXB + NWB, 256>>>(hidden, qkv_w, proj_w);

    qkv_hgemm_kernel<<<dim3(NQKV / 128, MTOT / 128), 512>>>(qkv_b);

    attn_mma_kernel<<<NWIN * NHEAD, 288>>>();

    proj_hgemm_kernel<<<dim3(DIM / 128, MTOT / 128), 512>>>(proj_b, out);
}

// round 16
// speedup vs baseline: 1.0032x; 1.0032x over previous
#include <cuda_runtime.h>
#include <cuda_fp16.h>
#include <cstdint>

// ---------------------------------------------------------------------------
// Florence2 window attention — all matmuls on mma.sync (fp16 in, fp32 acc).
// R16: V stored [wh][tok][d] like Q/K (coalesced half2 epilogue, one store
// path); attention transposes V into sVT during smem staging instead.
// GEMMs: R12-proven 512-thread config (established legacy-HMMA floor).
// ---------------------------------------------------------------------------

#define NWIN   128
#define NTOK   144
#define DIM    512
#define NHEAD  16
#define HDIM   32
#define MTOT   (NWIN * NTOK)     // 18432
#define NQKV   1536

#define SROW   72                // hgemm smem row stride in halves (144B)
#define BUFH  (128 * SROW)       // halves per buffer (per operand)
#define TSTR  (16 * SROW * 2)    // smem bytes between 16-row tiles

// ---------------- scratch (device globals; device-code refs only) ----------
__device__ __align__(16) __half g_x  [MTOT * DIM];
__device__ __align__(16) __half g_wq [NQKV * DIM];
__device__ __align__(16) __half g_wp [DIM * DIM];
__device__ __align__(16) __half g_qh [NWIN * NHEAD * NTOK * HDIM];  // Q*scale
__device__ __align__(16) __half g_kh [NWIN * NHEAD * NTOK * HDIM];  // K
__device__ __align__(16) __half g_vv [NWIN * NHEAD * NTOK * HDIM];  // V [tok][d]
__device__ __align__(16) __half g_ao [MTOT * DIM];

// ---------------- PTX helpers ----------------------------------------------
__device__ __forceinline__ uint32_t smem_u32(const void* p) {
    uint32_t a;
    asm("{ .reg .u64 t; cvta.to.shared.u64 t, %1; cvt.u32.u64 %0, t; }" : "=r"(a) : "l"(p));
    return a;
}
__device__ __forceinline__ void cp_async16(uint32_t s, const void* g) {
    asm volatile("cp.async.cg.shared.global [%0], [%1], 16;" :: "r"(s), "l"(g));
}
__device__ __forceinline__ void cp_commit() { asm volatile("cp.async.commit_group;"); }
__device__ __forceinline__ void cp_wait0()  { asm volatile("cp.async.wait_group 0;"); }

__device__ __forceinline__ void ldsm_x4(uint32_t* r, uint32_t addr) {
    asm volatile("ldmatrix.sync.aligned.m8n8.x4.shared.b16 {%0,%1,%2,%3}, [%4];"
        : "=r"(r[0]), "=r"(r[1]), "=r"(r[2]), "=r"(r[3]) : "r"(addr));
}
__device__ __forceinline__ void mma16816(float* d, const uint32_t* a,
                                         uint32_t b0, uint32_t b1) {
    asm volatile("mma.sync.aligned.m16n8k16.row.col.f32.f16.f16.f32 "
        "{%0,%1,%2,%3}, {%4,%5,%6,%7}, {%8,%9}, {%0,%1,%2,%3};"
        : "+f"(d[0]), "+f"(d[1]), "+f"(d[2]), "+f"(d[3])
        : "r"(a[0]), "r"(a[1]), "r"(a[2]), "r"(a[3]), "r"(b0), "r"(b1));
}

__device__ __forceinline__ int hidden_row_off(int m) {
    int win = m / NTOK, t = m % NTOK;
    int b = win >> 4, yw = (win >> 2) & 3, xw = win & 3;
    int y = yw * 12 + t / 12;
    int x = xw * 12 + t % 12;
    return ((b * 48 + y) * 48 + x) * DIM;
}

// ---------------------------------------------------------------------------
// merged conversion kernel: blocks [0, NXB) convert X; rest transpose weights
// ---------------------------------------------------------------------------
#define NXB (MTOT * 64 / 256)            // 4608
#define NWB ((NQKV / 32 + DIM / 32) * (DIM / 32))   // 1024

__global__ void convert_all_kernel(const float* __restrict__ hidden,
                                   const float* __restrict__ Wq,
                                   const float* __restrict__ Wp) {
    const int tid = threadIdx.x;
    if (blockIdx.x < NXB) {
        int idx = blockIdx.x * 256 + tid;
        int m = idx >> 6, seg = idx & 63;
        const float* src = hidden + hidden_row_off(m) + seg * 8;
        float4 f0 = *(const float4*)src;
        float4 f1 = *(const float4*)(src + 4);
        __align__(16) __half h[8];
        h[0] = __float2half(f0.x); h[1] = __float2half(f0.y);
        h[2] = __float2half(f0.z); h[3] = __float2half(f0.w);
        h[4] = __float2half(f1.x); h[5] = __float2half(f1.y);
        h[6] = __float2half(f1.z); h[7] = __float2half(f1.w);
        *(uint4*)&g_x[m * DIM + seg * 8] = *(uint4*)h;
        return;
    }
    __shared__ float t[32][33];
    const int r = blockIdx.x - NXB;
    const int bx = r & 63, by = r >> 6;
    const bool isP = bx >= (NQKV / 32);
    const float* __restrict__ W = isP ? Wp : Wq;
    const int N = isP ? DIM : NQKV;
    __half* __restrict__ outT = isP ? g_wp : g_wq;
    const int n0 = (isP ? bx - NQKV / 32 : bx) * 32;
    const int k0 = by * 32;
    const int tx = tid & 31, ty = tid >> 5;   // 32 x 8
    #pragma unroll
    for (int j = 0; j < 4; ++j)
        t[ty + 8 * j][tx] = W[(k0 + ty + 8 * j) * N + n0 + tx];
    __syncthreads();
    #pragma unroll
    for (int j = 0; j < 4; ++j)
        outT[(n0 + ty + 8 * j) * DIM + k0 + tx] = __float2half(t[tx][ty + 8 * j]);
}

// ---------------------------------------------------------------------------
// 512-thread HGEMM mainloop (16 warps, warp tile 32x32), f32-acc (R12-proven).
// ---------------------------------------------------------------------------
__device__ __forceinline__ void hgemm512_tile(
    const __half* __restrict__ A, const __half* __restrict__ B,
    int m0, int n0, float acc[2][4][4],
    __half (*sA)[BUFH], __half (*sB)[BUFH])
{
    const int tid = threadIdx.x;
    const int lane = tid & 31, wid = tid >> 5;
    const int wm = (wid & 3) * 32, wn = (wid >> 2) * 32;

    const uint32_t aBase = smem_u32(&sA[0][0]);
    const uint32_t bBase = smem_u32(&sB[0][0]);

    const __half* gA0 = A + (m0 + (tid >> 3)) * DIM + (tid & 7) * 8;
    const __half* gB0 = B + (n0 + (tid >> 3)) * DIM + (tid & 7) * 8;
    const uint32_t stA0 = aBase + (tid >> 3) * (SROW * 2) + (tid & 7) * 16;
    const uint32_t stB0 = bBase + (tid >> 3) * (SROW * 2) + (tid & 7) * 16;
    const int GS2 = 64 * DIM;
    const int SS2 = 64 * SROW * 2;

    const int la = lane & 7;
    const uint32_t aFrag0 = aBase + (wm + la + ((lane & 8) ? 8 : 0)) * (SROW * 2)
                          + (((lane & 16) ? 8 : 0)) * 2;
    const uint32_t bFrag0 = bBase + (wn + la + ((lane & 16) ? 8 : 0)) * (SROW * 2)
                          + (((lane & 8) ? 8 : 0)) * 2;

    cp_async16(stA0, gA0);             cp_async16(stB0, gB0);
    cp_async16(stA0 + SS2, gA0 + GS2); cp_async16(stB0 + SS2, gB0 + GS2);
    cp_commit();

    #pragma unroll 1
    for (int ch = 0; ch < 8; ++ch) {
        cp_wait0();
        __syncthreads();

        if (ch < 7) {
            const uint32_t bo = ((ch + 1) & 1) * (BUFH * 2);
            const int ko = (ch + 1) * 64;
            cp_async16(stA0 + bo, gA0 + ko);
            cp_async16(stB0 + bo, gB0 + ko);
            cp_async16(stA0 + bo + SS2, gA0 + ko + GS2);
            cp_async16(stB0 + bo + SS2, gB0 + ko + GS2);
            cp_commit();
        }

        const uint32_t aF = aFrag0 + (ch & 1) * (BUFH * 2);
        const uint32_t bF = bFrag0 + (ch & 1) * (BUFH * 2);
        #pragma unroll
        for (int s = 0; s < 4; ++s) {
            const uint32_t kb = s * 32;
            uint32_t a[2][4], b[2][4];
            ldsm_x4(a[0], aF + kb);
            ldsm_x4(a[1], aF + kb + TSTR);
            ldsm_x4(b[0], bF + kb);
            ldsm_x4(b[1], bF + kb + TSTR);
            #pragma unroll
            for (int i = 0; i < 2; ++i) {
                mma16816(acc[i][0], a[i], b[0][0], b[0][1]);
                mma16816(acc[i][1], a[i], b[0][2], b[0][3]);
                mma16816(acc[i][2], a[i], b[1][0], b[1][1]);
                mma16816(acc[i][3], a[i], b[1][2], b[1][3]);
            }
        }
    }
}

// ---------------------------------------------------------------------------
// Kernel: QKV GEMM — 512 threads. R16: single branch-free half2 store path
// (Q/K/V all stored [wh][tok][d]; sel + scale resolved once per CTA).
// ---------------------------------------------------------------------------
__global__ __launch_bounds__(512, 2)
void qkv_hgemm_kernel(const float* __restrict__ bias)
{
    __shared__ __align__(16) __half sA[2][BUFH];
    __shared__ __align__(16) __half sB[2][BUFH];

    float acc[2][4][4] = {};
    const int m0 = blockIdx.y * 128, n0 = blockIdx.x * 128;
    hgemm512_tile(g_x, g_wq, m0, n0, acc, sA, sB);

    const int tid = threadIdx.x, lane = tid & 31, wid = tid >> 5;
    const int g = lane >> 2, t = lane & 3;
    const int wm = (wid & 3) * 32, wn = (wid >> 2) * 32;

    const int sel = n0 >> 9;                       // constant per CTA
    __half* __restrict__ dst = (sel == 0) ? g_qh : (sel == 1) ? g_kh : g_vv;
    const float fs = (sel == 0) ? 0.1767766952966369f : 1.0f;   // 32^-0.5

    #pragma unroll
    for (int i = 0; i < 2; ++i) {
        #pragma unroll
        for (int h = 0; h < 2; ++h) {
            const int m = m0 + wm + i * 16 + h * 8 + g;
            const int win = m / NTOK, tok = m % NTOK;
            #pragma unroll
            for (int j = 0; j < 4; ++j) {
                const int n = n0 + wn + j * 8 + 2 * t;
                const int head = (n >> 5) & 15, d = n & 31;
                const int wh = (win << 4) + head;
                float vx = (acc[i][j][h * 2 + 0] + bias[n + 0]) * fs;
                float vy = (acc[i][j][h * 2 + 1] + bias[n + 1]) * fs;
                *(__half2*)&dst[(wh * NTOK + tok) * HDIM + d] =
                    __floats2half2_rn(vx, vy);
            }
        }
    }
}

// ---------------------------------------------------------------------------
// Kernel: tensor-core attention — R15 interleaved loop; R16: V transposed
// into sVT during staging (V now stored [tok][d] in gmem).
// 288 threads, 9 warps, 1 Q-tile/warp. Q frags direct from gmem.
// ---------------------------------------------------------------------------
#define QROW 40     // sK row stride (halves)
#define VROW 152    // sVT row stride (halves)

__global__ __launch_bounds__(288)
void attn_mma_kernel()
{
    __shared__ __align__(16) __half sK[NTOK * QROW];
    __shared__ __align__(16) __half sVT[HDIM * VROW];

    const int wh = blockIdx.x;
    const int tid = threadIdx.x, lane = tid & 31, wid = tid >> 5;
    const int g = lane >> 2, t = lane & 3;

    const __half* qp = g_qh + wh * (NTOK * HDIM);
    const __half* kp = g_kh + wh * (NTOK * HDIM);
    const __half* vp = g_vv + wh * (NTOK * HDIM);

    // K staging: contiguous uint4 copies
    for (int seg = tid; seg < 576; seg += 288) {
        int row = seg >> 2, sub = seg & 3;
        *(uint4*)&sK[row * QROW + sub * 8] = *(const uint4*)(kp + row * HDIM + sub * 8);
    }
    // V staging with transpose: read [tok][d] rows, scatter into sVT[d][tok]
    for (int seg = tid; seg < 576; seg += 288) {
        int tok = seg % NTOK, dseg = seg / NTOK;   // dseg 0..3
        uint4 v = *(const uint4*)(vp + tok * HDIM + dseg * 8);
        const __half* h = (const __half*)&v;
        #pragma unroll
        for (int k = 0; k < 8; ++k)
            sVT[(dseg * 8 + k) * VROW + tok] = h[k];
    }
    __syncthreads();

    const int win = wh >> 4, head = wh & 15;
    const int r = wid * 16 + g;            // warp -> its 16-row Q tile

    uint32_t qa[2][4];
    #pragma unroll
    for (int s = 0; s < 2; ++s) {
        const int c = s * 16 + 2 * t;
        qa[s][0] = *(const uint32_t*)&qp[ r      * HDIM + c    ];
        qa[s][1] = *(const uint32_t*)&qp[(r + 8) * HDIM + c    ];
        qa[s][2] = *(const uint32_t*)&qp[ r      * HDIM + c + 8];
        qa[s][3] = *(const uint32_t*)&qp[(r + 8) * HDIM + c + 8];
    }

    float acc[4][4] = {};
    float sum0 = 0.f, sum1 = 0.f;

    #pragma unroll
    for (int kk = 0; kk < 9; ++kk) {
        uint32_t pa[4];
        #pragma unroll
        for (int jj = 0; jj < 2; ++jj) {
            const int j = 2 * kk + jj;
            float sc[4] = {};
            const int rn = 8 * j + g;
            #pragma unroll
            for (int s = 0; s < 2; ++s) {
                const int c = s * 16 + 2 * t;
                uint32_t b0 = *(const uint32_t*)&sK[rn * QROW + c    ];
                uint32_t b1 = *(const uint32_t*)&sK[rn * QROW + c + 8];
                mma16816(sc, qa[s], b0, b1);
            }
            float e0 = __expf(sc[0]), e1 = __expf(sc[1]);
            float e2 = __expf(sc[2]), e3 = __expf(sc[3]);
            sum0 += e0 + e1; sum1 += e2 + e3;
            __half2 p01 = __floats2half2_rn(e0, e1);
            __half2 p23 = __floats2half2_rn(e2, e3);
            pa[2 * jj + 0] = *(uint32_t*)&p01;
            pa[2 * jj + 1] = *(uint32_t*)&p23;
        }
        #pragma unroll
        for (int nd = 0; nd < 4; ++nd) {
            const int rn = 8 * nd + g;
            uint32_t b0 = *(const uint32_t*)&sVT[rn * VROW + kk * 16 + 2 * t    ];
            uint32_t b1 = *(const uint32_t*)&sVT[rn * VROW + kk * 16 + 2 * t + 8];
            mma16816(acc[nd], pa, b0, b1);
        }
    }

    sum0 += __shfl_xor_sync(0xffffffffu, sum0, 1);
    sum0 += __shfl_xor_sync(0xffffffffu, sum0, 2);
    sum1 += __shfl_xor_sync(0xffffffffu, sum1, 1);
    sum1 += __shfl_xor_sync(0xffffffffu, sum1, 2);

    const float inv0 = 1.f / sum0, inv1 = 1.f / sum1;
    __half* o0 = g_ao + (win * NTOK + r) * DIM + head * HDIM;
    __half* o1 = o0 + 8 * DIM;
    #pragma unroll
    for (int nd = 0; nd < 4; ++nd) {
        const int d = 8 * nd + 2 * t;
        *(__half2*)&o0[d] = __floats2half2_rn(acc[nd][0] * inv0, acc[nd][1] * inv0);
        *(__half2*)&o1[d] = __floats2half2_rn(acc[nd][2] * inv1, acc[nd][3] * inv1);
    }
}

// ---------------------------------------------------------------------------
// Kernel: proj GEMM — 512 threads (R12-proven).
// ---------------------------------------------------------------------------
__global__ __launch_bounds__(512, 2)
void proj_hgemm_kernel(const float* __restrict__ bias, float* __restrict__ out)
{
    __shared__ __align__(16) __half sA[2][BUFH];
    __shared__ __align__(16) __half sB[2][BUFH];

    float acc[2][4][4] = {};
    const int m0 = blockIdx.y * 128, n0 = blockIdx.x * 128;
    hgemm512_tile(g_ao, g_wp, m0, n0, acc, sA, sB);

    const int tid = threadIdx.x, lane = tid & 31, wid = tid >> 5;
    const int g = lane >> 2, t = lane & 3;
    const int wm = (wid & 3) * 32, wn = (wid >> 2) * 32;

    #pragma unroll
    for (int i = 0; i < 2; ++i) {
        #pragma unroll
        for (int h = 0; h < 2; ++h) {
            const int m = m0 + wm + i * 16 + h * 8 + g;
            const int win = m / NTOK, tok = m % NTOK;
            const int b = win >> 4, yw = (win >> 2) & 3, xw = win & 3;
            const int y = yw * 12 + tok / 12;
            const int x = xw * 12 + tok % 12;
            float* orow = out + ((b * 2304 + y * 48 + x) << 9);
            #pragma unroll
            for (int j = 0; j < 4; ++j) {
                const int n = n0 + wn + j * 8 + 2 * t;
                float2 v;
                v.x = acc[i][j][h * 2 + 0] + bias[n + 0];
                v.y = acc[i][j][h * 2 + 1] + bias[n + 1];
                *(float2*)&orow[n] = v;
            }
        }
    }
}

// ---------------------------------------------------------------------------
extern "C" void kernel_launch(void* const* d_in, const int* in_sizes, int n_in,
                              void* d_out, int out_size)
{
    const float* hidden = (const float*)d_in[0];
    const float* qkv_w  = (const float*)d_in[1];
    const float* qkv_b  = (const float*)d_in[2];
    const float* proj_w = (const float*)d_in[3];
    const float* proj_b = (const float*)d_in[4];
    float* out = (float*)d_out;

    convert_all_kernel<<<NXB + NWB, 256>>>(hidden, qkv_w, proj_w);

    qkv_hgemm_kernel<<<dim3(NQKV / 128, MTOT / 128), 512>>>(qkv_b);

    attn_mma_kernel<<<NWIN * NHEAD, 288>>>();

    proj_hgemm_kernel<<<dim3(DIM / 128, MTOT / 128), 512>>>(proj_b, out);
}